// round 15
// baseline (speedup 1.0000x reference)
#include <cuda_runtime.h>

// Problem constants (match reference)
#define B   16
#define LX  2048
#define LR  1024
#define D   768
#define T   (LX + LR + 3)   // 3075
#define C8  (D / 8)         // 96 chunks of 32B per row
#define RPB 4               // rows per CTA
#define TPB 192             // 6 warps
#define CPB (RPB * C8)      // 384 chunks of 32B per CTA
#define KPT (CPB / TPB)     // 2 chunks per thread

// Hybrid width (R15): 256-bit streaming LOADS (best cold DRAM efficiency,
// halves load-issue count) + 128-bit intrinsic __stcs STORES (champion wall
// behavior, compiler-schedulable). Streaming policy both sides — measured
// best; working set 226MB > 126MB L2, nothing retainable across replays.

__device__ __forceinline__ void ldg_stream32(const void* p, float4& a, float4& b) {
    unsigned long long r0, r1, r2, r3;
    asm volatile("ld.global.nc.L2::evict_first.v4.b64 {%0,%1,%2,%3}, [%4];"
                 : "=l"(r0), "=l"(r1), "=l"(r2), "=l"(r3)
                 : "l"(p));
    a.x = __uint_as_float((unsigned)(r0));  a.y = __uint_as_float((unsigned)(r0 >> 32));
    a.z = __uint_as_float((unsigned)(r1));  a.w = __uint_as_float((unsigned)(r1 >> 32));
    b.x = __uint_as_float((unsigned)(r2));  b.y = __uint_as_float((unsigned)(r2 >> 32));
    b.z = __uint_as_float((unsigned)(r3));  b.w = __uint_as_float((unsigned)(r3 >> 32));
}

// out[b,t,:] =
//   t == 0                          : CLS
//   1 <= t <= lx[b]                 : X[b, t-1]
//   t == lx[b]+1                    : RING
//   lx[b]+2 <= t < lx[b]+2+lr[b]    : Xr[b, t-lx[b]-2]
//   t == lx[b]+lr[b]+2              : END
//   else                            : 0
__global__ __launch_bounds__(TPB) void assemble_kernel(
    const float*  __restrict__ X,
    const float*  __restrict__ Xr,
    const float4* __restrict__ CLS,
    const float4* __restrict__ RING,
    const float4* __restrict__ END,
    const int*    __restrict__ lx,
    const int*    __restrict__ lr,
    float4*       __restrict__ out)
{
    const int tid = threadIdx.x;

    float4 va[KPT], vb[KPT];

    // Gather phase: both 32B chunks loaded before any store (MLP>=2 at
    // 256-bit width = 4 outstanding 128B sectors per thread).
    #pragma unroll
    for (int k = 0; k < KPT; k++) {
        const int chunk = tid + k * TPB;          // 0..383 (32B units)
        const int rl    = chunk / C8;             // row within CTA (0..3)
        const int c     = chunk - rl * C8;        // 0..95
        const int row   = blockIdx.x * RPB + rl;
        const int b     = row / T;                // const-div -> mul/shift
        const int t     = row - b * T;

        const int lxb = __ldg(&lx[b]);
        const int lrb = __ldg(&lr[b]);

        if (t == 0) {
            va[k] = CLS[2 * c];  vb[k] = CLS[2 * c + 1];
        } else if (t <= lxb) {
            ldg_stream32(X + ((long)b * LX + (t - 1)) * D + c * 8, va[k], vb[k]);
        } else if (t == lxb + 1) {
            va[k] = RING[2 * c]; vb[k] = RING[2 * c + 1];
        } else if (t < lxb + 2 + lrb) {
            ldg_stream32(Xr + ((long)b * LR + (t - lxb - 2)) * D + c * 8, va[k], vb[k]);
        } else if (t == lxb + lrb + 2) {
            va[k] = END[2 * c];  vb[k] = END[2 * c + 1];
        } else {
            va[k] = make_float4(0.f, 0.f, 0.f, 0.f);
            vb[k] = va[k];
        }
    }

    // Store phase: 128-bit streaming stores (intrinsic -> compiler keeps
    // scheduling freedom; no asm ordering barrier).
    const long base = (long)blockIdx.x * CPB * 2;   // in float4 units
    #pragma unroll
    for (int k = 0; k < KPT; k++) {
        const long o = base + (long)(tid + k * TPB) * 2;
        __stcs(&out[o],     va[k]);
        __stcs(&out[o + 1], vb[k]);
    }
}

extern "C" void kernel_launch(void* const* d_in, const int* in_sizes, int n_in,
                              void* d_out, int out_size)
{
    const float*  X    = (const float*)d_in[0];
    const float*  Xr   = (const float*)d_in[1];
    const float4* CLS  = (const float4*)d_in[2];
    const float4* RING = (const float4*)d_in[3];
    const float4* END  = (const float4*)d_in[4];
    const int*    lx   = (const int*)d_in[5];
    const int*    lr   = (const int*)d_in[6];
    float4*       out  = (float4*)d_out;

    dim3 grid((B * T) / RPB);   // 12300 CTAs
    dim3 block(TPB);            // 192 threads
    assemble_kernel<<<grid, block>>>(X, Xr, CLS, RING, END, lx, lr, out);
}

// round 16
// speedup vs baseline: 1.0427x; 1.0427x over previous
#include <cuda_runtime.h>

// Problem constants (match reference)
#define B   16
#define LX  2048
#define LR  1024
#define D   768
#define T   (LX + LR + 3)   // 3075
#define D4  (D / 4)         // 192 float4 per row
#define RPB 4               // rows per CTA (B*T = 49200 divisible by 4)
#define TPB 256             // 8 warps -> 32 warps/SM at 4 CTAs (100% theoretical occ)
#define CPB (RPB * D4)      // 768 chunks per CTA
#define KPT (CPB / TPB)     // 3 chunks per thread

// FINAL (session champion, R12): wall 39.392us, ncu 33.95us, occ 82.6%,
// regs 22. The problem moves ~226MB/replay of compulsory mixed read/write
// HBM traffic; this kernel runs at ~5.7TB/s effective, ~90% of the
// measured mixed-stream ceiling. All policy/width/structure alternatives
// (15 rounds) tied or regressed.
//
// out[b,t,:] =
//   t == 0                          : CLS
//   1 <= t <= lx[b]                 : X[b, t-1]
//   t == lx[b]+1                    : RING
//   lx[b]+2 <= t < lx[b]+2+lr[b]    : Xr[b, t-lx[b]-2]
//   t == lx[b]+lr[b]+2              : END
//   else                            : 0
//
// Policy: streaming both sides (__ldcs/__stcs) — measured best; working set
// 226MB > 126MB L2, nothing retainable across graph replays.
// Structure: 256-thread CTAs, flat chunk indexing over 4 contiguous rows.
// 192 % 32 == 0 so each warp's 32 consecutive chunks sit in ONE row ->
// warp-uniform branching, fully coalesced 128B accesses, MLP=3.
__global__ __launch_bounds__(TPB) void assemble_kernel(
    const float4* __restrict__ X,
    const float4* __restrict__ Xr,
    const float4* __restrict__ CLS,
    const float4* __restrict__ RING,
    const float4* __restrict__ END,
    const int*    __restrict__ lx,
    const int*    __restrict__ lr,
    float4*       __restrict__ out)
{
    const int  tid   = threadIdx.x;
    const long base  = (long)blockIdx.x * CPB;   // first chunk of this CTA

    float4 v[KPT];

    #pragma unroll
    for (int k = 0; k < KPT; k++) {
        const int chunk = tid + k * TPB;          // 0..767
        const int rl    = chunk / D4;             // row within CTA (0..3)
        const int c     = chunk - rl * D4;        // 0..191
        const int row   = blockIdx.x * RPB + rl;
        const int b     = row / T;                // const-div -> mul/shift
        const int t     = row - b * T;

        const int lxb = __ldg(&lx[b]);
        const int lrb = __ldg(&lr[b]);

        if (t == 0) {
            v[k] = CLS[c];
        } else if (t <= lxb) {
            v[k] = __ldcs(&X[((long)b * LX + (t - 1)) * D4 + c]);
        } else if (t == lxb + 1) {
            v[k] = RING[c];
        } else if (t < lxb + 2 + lrb) {
            v[k] = __ldcs(&Xr[((long)b * LR + (t - lxb - 2)) * D4 + c]);
        } else if (t == lxb + lrb + 2) {
            v[k] = END[c];
        } else {
            v[k] = make_float4(0.f, 0.f, 0.f, 0.f);
        }
    }

    #pragma unroll
    for (int k = 0; k < KPT; k++) {
        __stcs(&out[base + tid + k * TPB], v[k]);
    }
}

extern "C" void kernel_launch(void* const* d_in, const int* in_sizes, int n_in,
                              void* d_out, int out_size)
{
    const float4* X    = (const float4*)d_in[0];
    const float4* Xr   = (const float4*)d_in[1];
    const float4* CLS  = (const float4*)d_in[2];
    const float4* RING = (const float4*)d_in[3];
    const float4* END  = (const float4*)d_in[4];
    const int*    lx   = (const int*)d_in[5];
    const int*    lr   = (const int*)d_in[6];
    float4*       out  = (float4*)d_out;

    dim3 grid((B * T) / RPB);   // 12300 CTAs
    dim3 block(TPB);            // 256 threads
    assemble_kernel<<<grid, block>>>(X, Xr, CLS, RING, END, lx, lr, out);
}